// round 13
// baseline (speedup 1.0000x reference)
#include <cuda_runtime.h>

#define B_ 256
#define T_ 1024
#define K_ 128

__device__ float g_denom[B_];
__device__ float g_num[B_];

typedef unsigned long long u64;

__device__ __forceinline__ void ffma2(u64 &d, u64 a, u64 b) {
    asm("fma.rn.f32x2 %0, %1, %2, %0;" : "+l"(d) : "l"(a), "l"(b));
}
__device__ __forceinline__ u64 fadd2(u64 a, u64 b) {
    u64 r; asm("add.rn.f32x2 %0, %1, %2;" : "=l"(r) : "l"(a), "l"(b)); return r;
}
__device__ __forceinline__ u64 pack2(float lo, float hi) {
    u64 r; asm("mov.b64 %0, {%1, %2};" : "=l"(r) : "f"(lo), "f"(hi)); return r;
}
__device__ __forceinline__ void unpack2(u64 v, float &lo, float &hi) {
    asm("mov.b64 {%0, %1}, %2;" : "=f"(lo), "=f"(hi) : "l"(v));
}

// ---------------------------------------------------------------------------
// Fused forward + numerator (one launch):
//   blocks [0,128):   forward, 2 batches/block (2 groups x 128 threads)
//   blocks [128,384): numerator, 1 batch/block
//
// Forward group: thread owns states jA / jA+64 and i-half h; permuted p
// layout gives 1-wavefront LDS.128; halves combine via shfl_xor(16).
// NEW vs R12 (owner-computes-uniforms): rcp(p0) computed ONCE per group by
// the state-0 owner in the previous step's tail and broadcast via smem;
// log(p0) and the C accumulation live only in the owner thread. Removes 2
// uniform MUFUs + FADD + SEL from 255/256 threads (~32 MUFU SMSP-cyc/step).
// ---------------------------------------------------------------------------
__global__ void __launch_bounds__(256, 1) fused_kernel(
    const float* inp, const float* trans, const int* tags, const int* mask) {
    const int tid = threadIdx.x;

    __shared__ __align__(16) float pbuf[2][2][K_];   // [group][buffer][slot]
    __shared__ float srp[2][2];                      // [group][buffer]: 1/p0
    __shared__ int smask[2][T_];
    __shared__ float sf[256];
    __shared__ int   si[256];

    if (blockIdx.x < 128) {
        // ================= forward =================
        const int g    = tid >> 7;            // group 0/1
        const int t128 = tid & 127;
        const int w    = t128 >> 5;           // warp-in-group 0..3
        const int l    = t128 & 31;
        const int h    = l >> 4;              // i-half
        const int jlo  = w * 16 + (l & 15);   // 0..63
        const int jA = jlo, jB = jlo + 64;
        const int b  = blockIdx.x * 2 + g;
        const bool owner = (t128 == 0);       // owns state 0 (slot 0)
        // permuted store slot: j=4q+r -> slot 4*(2*(q&15)+(q>>4)) + r
        const int posA = ((jlo >> 2) << 3) | (jlo & 3);   // posB = posA + 4

        for (int t = t128; t < T_; t += 128)
            smask[g][t] = mask[(size_t)b * T_ + t];

        // E columns jA/jB for my i-half, packed pairs matching quad order.
        u64 EA[32], EB[32];
#pragma unroll
        for (int m = 0; m < 32; m++) {
            const int i = (h << 6) + 2 * m;
            EA[m] = pack2(__expf(trans[i * K_ + jA]),
                          __expf(trans[(i + 1) * K_ + jA]));
            EB[m] = pack2(__expf(trans[i * K_ + jB]),
                          __expf(trans[(i + 1) * K_ + jB]));
        }

        const float* ebA = inp + (size_t)b * T_ * K_ + jA;
        const float* ebB = inp + (size_t)b * T_ * K_ + jB;

        float pcA = __expf(ebA[0]);           // t = 0
        float pcB = __expf(ebB[0]);
        if (h == 0) { pbuf[g][0][posA] = pcA; pbuf[g][0][posA + 4] = pcB; }
        if (owner)  srp[g][0] = __frcp_rn(pcA);   // rcp(p0) for step 1
        float C = 0.0f;                            // live only in owner

        // dual emission rings: ee = exp(emit[t]); r1..r4 raw emit[t+1..t+4]
        float eeA = __expf(ebA[K_]),      eeB = __expf(ebB[K_]);
        float r1A = ebA[2 * K_], r1B = ebB[2 * K_];
        float r2A = ebA[3 * K_], r2B = ebB[3 * K_];
        float r3A = ebA[4 * K_], r3B = ebB[4 * K_];
        float r4A = ebA[5 * K_], r4B = ebB[5 * K_];
        __syncthreads();                      // covers smask + pbuf + srp init
        int mnext = smask[g][1];

        const int bar_id = g + 1;
        int cur = 0;
#pragma unroll 2
        for (int t = 1; t < T_; t++) {
            const int i5 = (t + 5 < T_) ? (t + 5) : (T_ - 1);   // clamped
            const float rnA = ebA[(size_t)i5 << 7];
            const float rnB = ebB[(size_t)i5 << 7];
            const float eA2 = __expf(r1A);    // exp(emit[t+1]), aged 4 steps
            const float eB2 = __expf(r1B);
            const int   mc  = mnext;
            mnext = smask[g][(t + 1 < T_) ? (t + 1) : (T_ - 1)];

            const float rp0 = srp[g][cur];    // broadcast LDS: 1/p0

            const ulonglong2* pvh =
                (const ulonglong2*)pbuf[g][cur] + h;   // +16B for half 1
            u64 aA0 = 0ULL, aA1 = 0ULL, aA2 = 0ULL, aA3 = 0ULL;
            u64 aB0 = 0ULL, aB1 = 0ULL, aB2 = 0ULL, aB3 = 0ULL;
#pragma unroll
            for (int k = 0; k < 16; k += 2) {
                const ulonglong2 u = pvh[2 * k];          // p[64h+4k..+3]
                ffma2(aA0, u.x, EA[2 * k]);     ffma2(aA1, u.y, EA[2 * k + 1]);
                ffma2(aB0, u.x, EB[2 * k]);     ffma2(aB1, u.y, EB[2 * k + 1]);
                const ulonglong2 v = pvh[2 * k + 2];      // next quad
                ffma2(aA2, v.x, EA[2 * k + 2]); ffma2(aA3, v.y, EA[2 * k + 3]);
                ffma2(aB2, v.x, EB[2 * k + 2]); ffma2(aB3, v.y, EB[2 * k + 3]);
            }
            const u64 rA = fadd2(fadd2(aA0, aA1), fadd2(aA2, aA3));
            const u64 rB = fadd2(fadd2(aB0, aB1), fadd2(aB2, aB3));
            float loA, hiA, loB, hiB;
            unpack2(rA, loA, hiA);
            unpack2(rB, loB, hiB);
            // pack (hA, hB) and do one 64-bit butterfly + one packed add
            u64 hAB = pack2(loA + hiA, loB + hiB);
            const u64 oAB = __shfl_xor_sync(0xffffffffu, hAB, 16);
            float sA, sB; unpack2(fadd2(hAB, oAB), sA, sB);

            const float pnA = sA * (eeA * rp0);
            const float pnB = sB * (eeB * rp0);
            const float pwA = mc ? pnA : pcA;
            const float pwB = mc ? pnB : pcB;

            cur ^= 1;
            if (h == 0) {
                pbuf[g][cur][posA]     = pwA;
                pbuf[g][cur][posA + 4] = pwB;
            }
            if (owner) {                       // uniforms: one thread only
                srp[g][cur] = __frcp_rn(pwA);  // rcp(new p0) for next step
                if (mc) C += __logf(pcA);      // log(old p0), off-path
            }
            pcA = pwA; pcB = pwB;
            asm volatile("bar.sync %0, 128;" :: "r"(bar_id) : "memory");

            eeA = eA2; eeB = eB2;             // rotate rings
            r1A = r2A; r2A = r3A; r3A = r4A; r4A = rnA;
            r1B = r2B; r2B = r3B; r3B = r4B; r4B = rnB;
        }

        if (owner) {
            float sum = 0.0f;                 // fixed (permuted) order: determ.
            for (int i = 0; i < K_; i++) sum += pbuf[g][cur][i];
            g_denom[b] = C + __logf(sum);
        }
    } else {
        // ================= numerator =================
        const int b = blockIdx.x - 128;       // 0..255
        const int*   tb = tags + (size_t)b * T_;
        const int*   mb = mask + (size_t)b * T_;
        const float* eb = inp  + (size_t)b * T_ * K_;

        float s = 0.0f;
        int msum = 0;
        for (int t = tid; t < T_; t += 256) {
            msum += mb[t];
            if (t < T_ - 1) {
                const int tg  = tb[t]     & (K_ - 1);
                const int tg1 = tb[t + 1] & (K_ - 1);
                s += trans[tg * K_ + tg1] * (float)mb[t + 1]
                   + eb[(size_t)t * K_ + tg] * (float)mb[t];
            }
        }
        sf[tid] = s; si[tid] = msum;
        __syncthreads();
        for (int off = 128; off > 0; off >>= 1) {
            if (tid < off) { sf[tid] += sf[tid + off]; si[tid] += si[tid + off]; }
            __syncthreads();
        }
        if (tid == 0) {
            int last_idx = si[0] - 1;
            if (last_idx < 0)   last_idx = 0;
            if (last_idx >= T_) last_idx = T_ - 1;
            const int lt = tb[last_idx] & (K_ - 1);
            g_num[b] = sf[0]
                     + eb[(size_t)(T_ - 1) * K_ + lt] * (float)mb[T_ - 1];
        }
    }
}

// ---------------------------------------------------------------------------
__global__ void final_kernel(float* out) {
    __shared__ float sd[B_];
    const int t = threadIdx.x;
    sd[t] = g_num[t] - g_denom[t];
    __syncthreads();
    for (int off = 128; off > 0; off >>= 1) {
        if (t < off) sd[t] += sd[t + off];
        __syncthreads();
    }
    if (t == 0) out[0] = sd[0];
}

// ---------------------------------------------------------------------------
extern "C" void kernel_launch(void* const* d_in, const int* in_sizes, int n_in,
                              void* d_out, int out_size) {
    const float* inp   = (const float*)d_in[0];   // (B,T,K) f32
    const float* trans = (const float*)d_in[1];   // (K,K)   f32
    const int*   tags  = (const int*)d_in[2];     // (B,T)   i32
    const int*   mask  = (const int*)d_in[3];     // (B,T)   i32
    float* out = (float*)d_out;

    fused_kernel<<<128 + B_, 256>>>(inp, trans, tags, mask);
    final_kernel<<<1, B_>>>(out);
}

// round 14
// speedup vs baseline: 1.0421x; 1.0421x over previous
#include <cuda_runtime.h>

#define B_ 256
#define T_ 1024
#define K_ 128
#define NBLOCKS_ (128 + B_)

__device__ float g_denom[B_];
__device__ float g_num[B_];
__device__ unsigned int g_count = 0;

typedef unsigned long long u64;

__device__ __forceinline__ void ffma2(u64 &d, u64 a, u64 b) {
    asm("fma.rn.f32x2 %0, %1, %2, %0;" : "+l"(d) : "l"(a), "l"(b));
}
__device__ __forceinline__ u64 fadd2(u64 a, u64 b) {
    u64 r; asm("add.rn.f32x2 %0, %1, %2;" : "=l"(r) : "l"(a), "l"(b)); return r;
}
__device__ __forceinline__ u64 pack2(float lo, float hi) {
    u64 r; asm("mov.b64 %0, {%1, %2};" : "=l"(r) : "f"(lo), "f"(hi)); return r;
}
__device__ __forceinline__ void unpack2(u64 v, float &lo, float &hi) {
    asm("mov.b64 {%0, %1}, %2;" : "=f"(lo), "=f"(hi) : "l"(v));
}

// ---------------------------------------------------------------------------
// Single-launch fused kernel:
//   blocks [0,128):   forward, 2 batches/block (2 groups x 128 threads)
//   blocks [128,384): numerator, 1 batch/block
//   last block to finish: reduces sum_b(num_b - denom_b) -> out (ticket
//   pattern: per-writer threadfence -> syncthreads -> atomic ticket; fixed
//   reduction order => deterministic; counter reset for graph replay).
//
// Forward math (R12, the 379us best — R13's owner-serialized uniforms
// reverted): p'_j = (sum_i p_i E_ij) * exp(emit_j) * rcp(p_0); C += log(p_0).
// Per-thread parallel rcp/log (off the barrier path). 2 states/thread,
// permuted p layout -> 1-wavefront broadcast LDS.128; i-halves combine via
// one packed shfl_xor(16). Dual 4-deep emission rings hide DRAM latency.
// ---------------------------------------------------------------------------
__global__ void __launch_bounds__(256, 1) fused_kernel(
    const float* inp, const float* trans, const int* tags, const int* mask,
    float* out) {
    const int tid = threadIdx.x;

    __shared__ __align__(16) float pbuf[2][2][K_];   // [group][buffer][slot]
    __shared__ int smask[2][T_];
    __shared__ float sf[256];
    __shared__ int   si[256];
    __shared__ unsigned int s_rank;

    if (blockIdx.x < 128) {
        // ================= forward =================
        const int g    = tid >> 7;            // group 0/1
        const int t128 = tid & 127;
        const int w    = t128 >> 5;           // warp-in-group 0..3
        const int l    = t128 & 31;
        const int h    = l >> 4;              // i-half
        const int jlo  = w * 16 + (l & 15);   // 0..63
        const int jA = jlo, jB = jlo + 64;
        const int b  = blockIdx.x * 2 + g;
        // permuted store slot: j=4q+r -> slot 4*(2*(q&15)+(q>>4)) + r
        const int posA = ((jlo >> 2) << 3) | (jlo & 3);   // posB = posA + 4

        for (int t = t128; t < T_; t += 128)
            smask[g][t] = mask[(size_t)b * T_ + t];

        // E columns jA/jB for my i-half, packed pairs matching quad order.
        u64 EA[32], EB[32];
#pragma unroll
        for (int m = 0; m < 32; m++) {
            const int i = (h << 6) + 2 * m;
            EA[m] = pack2(__expf(trans[i * K_ + jA]),
                          __expf(trans[(i + 1) * K_ + jA]));
            EB[m] = pack2(__expf(trans[i * K_ + jB]),
                          __expf(trans[(i + 1) * K_ + jB]));
        }

        const float* ebA = inp + (size_t)b * T_ * K_ + jA;
        const float* ebB = inp + (size_t)b * T_ * K_ + jB;

        float pcA = __expf(ebA[0]);           // t = 0
        float pcB = __expf(ebB[0]);
        if (h == 0) { pbuf[g][0][posA] = pcA; pbuf[g][0][posA + 4] = pcB; }
        float C = 0.0f;

        // dual emission rings: ee = exp(emit[t]); r1..r4 raw emit[t+1..t+4]
        float eeA = __expf(ebA[K_]),      eeB = __expf(ebB[K_]);
        float r1A = ebA[2 * K_], r1B = ebB[2 * K_];
        float r2A = ebA[3 * K_], r2B = ebB[3 * K_];
        float r3A = ebA[4 * K_], r3B = ebB[4 * K_];
        float r4A = ebA[5 * K_], r4B = ebB[5 * K_];
        __syncthreads();                      // covers smask + pbuf init
        int mnext = smask[g][1];

        const int bar_id = g + 1;
        int cur = 0;
#pragma unroll 2
        for (int t = 1; t < T_; t++) {
            const int i5 = (t + 5 < T_) ? (t + 5) : (T_ - 1);   // clamped
            const float rnA = ebA[(size_t)i5 << 7];
            const float rnB = ebB[(size_t)i5 << 7];
            const float eA2 = __expf(r1A);    // exp(emit[t+1]), aged 4 steps
            const float eB2 = __expf(r1B);
            const int   mc  = mnext;
            mnext = smask[g][(t + 1 < T_) ? (t + 1) : (T_ - 1)];

            const float p0  = pbuf[g][cur][0];     // slot 0 == state 0
            const float rp0 = __frcp_rn(p0);       // || with FMA tree
            const float lp0 = __logf(p0);          // off-path (C only)

            const ulonglong2* pvh =
                (const ulonglong2*)pbuf[g][cur] + h;   // +16B for half 1
            u64 aA0 = 0ULL, aA1 = 0ULL, aA2 = 0ULL, aA3 = 0ULL;
            u64 aB0 = 0ULL, aB1 = 0ULL, aB2 = 0ULL, aB3 = 0ULL;
#pragma unroll
            for (int k = 0; k < 16; k += 2) {
                const ulonglong2 u = pvh[2 * k];          // p[64h+4k..+3]
                ffma2(aA0, u.x, EA[2 * k]);     ffma2(aA1, u.y, EA[2 * k + 1]);
                ffma2(aB0, u.x, EB[2 * k]);     ffma2(aB1, u.y, EB[2 * k + 1]);
                const ulonglong2 v = pvh[2 * k + 2];      // next quad
                ffma2(aA2, v.x, EA[2 * k + 2]); ffma2(aA3, v.y, EA[2 * k + 3]);
                ffma2(aB2, v.x, EB[2 * k + 2]); ffma2(aB3, v.y, EB[2 * k + 3]);
            }
            const u64 rA = fadd2(fadd2(aA0, aA1), fadd2(aA2, aA3));
            const u64 rB = fadd2(fadd2(aB0, aB1), fadd2(aB2, aB3));
            float loA, hiA, loB, hiB;
            unpack2(rA, loA, hiA);
            unpack2(rB, loB, hiB);
            // pack (hA, hB): one 64-bit butterfly + one packed add
            u64 hAB = pack2(loA + hiA, loB + hiB);
            const u64 oAB = __shfl_xor_sync(0xffffffffu, hAB, 16);
            float sA, sB; unpack2(fadd2(hAB, oAB), sA, sB);

            const float pnA = sA * (eeA * rp0);
            const float pnB = sB * (eeB * rp0);
            const float pwA = mc ? pnA : pcA;
            const float pwB = mc ? pnB : pcB;
            C += mc ? lp0 : 0.0f;

            cur ^= 1;
            if (h == 0) {
                pbuf[g][cur][posA]     = pwA;
                pbuf[g][cur][posA + 4] = pwB;
            }
            pcA = pwA; pcB = pwB;
            asm volatile("bar.sync %0, 128;" :: "r"(bar_id) : "memory");

            eeA = eA2; eeB = eB2;             // rotate rings
            r1A = r2A; r2A = r3A; r3A = r4A; r4A = rnA;
            r1B = r2B; r2B = r3B; r3B = r4B; r4B = rnB;
        }

        if (t128 == 0) {
            float sum = 0.0f;                 // fixed (permuted) order: determ.
            for (int i = 0; i < K_; i++) sum += pbuf[g][cur][i];
            g_denom[b] = C + __logf(sum);
            __threadfence();                  // writer-side release
        }
    } else {
        // ================= numerator =================
        const int b = blockIdx.x - 128;       // 0..255
        const int*   tb = tags + (size_t)b * T_;
        const int*   mb = mask + (size_t)b * T_;
        const float* eb = inp  + (size_t)b * T_ * K_;

        float s = 0.0f;
        int msum = 0;
        for (int t = tid; t < T_; t += 256) {
            msum += mb[t];
            if (t < T_ - 1) {
                const int tg  = tb[t]     & (K_ - 1);
                const int tg1 = tb[t + 1] & (K_ - 1);
                s += trans[tg * K_ + tg1] * (float)mb[t + 1]
                   + eb[(size_t)t * K_ + tg] * (float)mb[t];
            }
        }
        sf[tid] = s; si[tid] = msum;
        __syncthreads();
        for (int off = 128; off > 0; off >>= 1) {
            if (tid < off) { sf[tid] += sf[tid + off]; si[tid] += si[tid + off]; }
            __syncthreads();
        }
        if (tid == 0) {
            int last_idx = si[0] - 1;
            if (last_idx < 0)   last_idx = 0;
            if (last_idx >= T_) last_idx = T_ - 1;
            const int lt = tb[last_idx] & (K_ - 1);
            g_num[b] = sf[0]
                     + eb[(size_t)(T_ - 1) * K_ + lt] * (float)mb[T_ - 1];
            __threadfence();                  // writer-side release
        }
    }

    // ---------------- completion ticket + final reduction ----------------
    __syncthreads();                          // all block writes fenced above
    if (tid == 0) s_rank = atomicAdd(&g_count, 1u);
    __syncthreads();
    if (s_rank == NBLOCKS_ - 1) {             // last block: everything visible
        __threadfence();                      // acquire side
        sf[tid] = g_num[tid] - g_denom[tid];  // tid == batch (256 threads)
        __syncthreads();
        for (int off = 128; off > 0; off >>= 1) {
            if (tid < off) sf[tid] += sf[tid + off];
            __syncthreads();
        }
        if (tid == 0) {
            out[0] = sf[0];
            g_count = 0;                      // reset for next graph replay
        }
    }
}

// ---------------------------------------------------------------------------
extern "C" void kernel_launch(void* const* d_in, const int* in_sizes, int n_in,
                              void* d_out, int out_size) {
    const float* inp   = (const float*)d_in[0];   // (B,T,K) f32
    const float* trans = (const float*)d_in[1];   // (K,K)   f32
    const int*   tags  = (const int*)d_in[2];     // (B,T)   i32
    const int*   mask  = (const int*)d_in[3];     // (B,T)   i32
    float* out = (float*)d_out;

    fused_kernel<<<NBLOCKS_, 256>>>(inp, trans, tags, mask, out);
}